// round 11
// baseline (speedup 1.0000x reference)
#include <cuda_runtime.h>
#include <cuda_fp16.h>
#include <cstdint>

#define N_NODES 50000
#define N_EDGES 600000
#define IN_F    128
#define H_F     256
#define NSB     ((N_NODES + 255) / 256)   // 196 scan blocks

// ---------------- scratch (static device globals; no allocation) -------------
__device__ int   g_deg_out_i[N_NODES];
__device__ int   g_deg_in_i[N_NODES];
__device__ float g_norm_src[N_NODES];
__device__ float g_norm_dst[N_NODES];
__device__ int   g_row_ptr[N_NODES + 1];
__device__ int   g_cursor[N_NODES];
__device__ int   g_csr_src[N_EDGES];
__device__ int   g_block_sums[NSB];
// fp16 copy of x (halves gather L2 traffic)
__device__ __align__(16) __half g_x_h[(size_t)N_NODES * IN_F];
// fp16 weights, transposed to [n][k] (k contiguous)
__device__ __align__(16) __half g_Wc_h[H_F * IN_F];
__device__ __align__(16) __half g_Wf_h[H_F * H_F];
__device__ __align__(16) __half g_Wf2_h[H_F * H_F];

// ---------------- helpers -------------------------------------------------------
__device__ __forceinline__ uint32_t smem_to_u32(const void* p) {
    uint32_t a;
    asm("{ .reg .u64 t; cvta.to.shared.u64 t, %1; cvt.u32.u64 %0, t; }"
        : "=r"(a) : "l"(p));
    return a;
}
__device__ __forceinline__ void cp16(uint32_t saddr, const void* g) {
    asm volatile("cp.async.cg.shared.global [%0], [%1], 16;"
                 :: "r"(saddr), "l"(g) : "memory");
}
#define CP_COMMIT() asm volatile("cp.async.commit_group;" ::: "memory")
#define CP_WAIT0()  asm volatile("cp.async.wait_group 0;" ::: "memory")
#define CP_WAIT1()  asm volatile("cp.async.wait_group 1;" ::: "memory")

// ---------------- init: zero degrees + fp16 weights + fp16 x -------------------
__global__ void init_kernel(const float* __restrict__ x,
                            const float* __restrict__ Wc,
                            const float* __restrict__ Wf,
                            const float* __restrict__ Wf2) {
    const int gs = gridDim.x * blockDim.x;
    int t0 = blockIdx.x * blockDim.x + threadIdx.x;
    for (int i = t0; i < N_NODES; i += gs) {
        g_deg_out_i[i] = 0; g_deg_in_i[i] = 0;
    }
    for (int i = t0; i < H_F * IN_F; i += gs) {
        int n = i / IN_F, k = i % IN_F;
        g_Wc_h[i] = __float2half_rn(Wc[k * H_F + n]);
    }
    for (int i = t0; i < H_F * H_F; i += gs) {
        int n = i / H_F, k = i % H_F;
        g_Wf_h[i]  = __float2half_rn(Wf[k * H_F + n]);
        g_Wf2_h[i] = __float2half_rn(Wf2[k * H_F + n]);
    }
    // x -> fp16, 2 floats per thread-iter
    const int XH = (N_NODES * IN_F) / 2;
    const float2* x2 = reinterpret_cast<const float2*>(x);
    __half2* xh2 = reinterpret_cast<__half2*>(g_x_h);
    for (int i = t0; i < XH; i += gs) {
        float2 v = x2[i];
        xh2[i] = __floats2half2_rn(v.x, v.y);
    }
}

// ---------------- degree accumulation ------------------------------------------
__global__ void degree_kernel(const int* __restrict__ src,
                              const int* __restrict__ dst) {
    int e = blockIdx.x * blockDim.x + threadIdx.x;
    if (e >= N_EDGES) return;
    atomicAdd(&g_deg_out_i[src[e]], 1);
    atomicAdd(&g_deg_in_i[dst[e]], 1);
}

// ---------------- 3-phase parallel scan of deg_in -> row_ptr ------------------
__global__ void scan_phaseA() {
    __shared__ int ws[8];
    int t = threadIdx.x, lane = t & 31, wid = t >> 5;
    int i = blockIdx.x * 256 + t;
    int v = (i < N_NODES) ? g_deg_in_i[i] : 0;
    #pragma unroll
    for (int off = 16; off > 0; off >>= 1)
        v += __shfl_down_sync(0xffffffffu, v, off);
    if (lane == 0) ws[wid] = v;
    __syncthreads();
    if (t == 0) {
        int s = 0;
        #pragma unroll
        for (int w = 0; w < 8; w++) s += ws[w];
        g_block_sums[blockIdx.x] = s;
    }
}
__global__ void scan_phaseB() {
    __shared__ int ws[8];
    int t = threadIdx.x, lane = t & 31, wid = t >> 5;
    int v = (t < NSB) ? g_block_sums[t] : 0;
    int x = v;
    #pragma unroll
    for (int off = 1; off < 32; off <<= 1) {
        int tm = __shfl_up_sync(0xffffffffu, x, off);
        if (lane >= off) x += tm;
    }
    if (lane == 31) ws[wid] = x;
    __syncthreads();
    int add = 0;
    for (int w = 0; w < wid; w++) add += ws[w];
    if (t < NSB) g_block_sums[t] = x + add - v;
}
__global__ void scan_phaseC() {
    __shared__ int ws[8];
    int t = threadIdx.x, lane = t & 31, wid = t >> 5;
    int i = blockIdx.x * 256 + t;
    int v = (i < N_NODES) ? g_deg_in_i[i] : 0;
    int x = v;
    #pragma unroll
    for (int off = 1; off < 32; off <<= 1) {
        int tm = __shfl_up_sync(0xffffffffu, x, off);
        if (lane >= off) x += tm;
    }
    if (lane == 31) ws[wid] = x;
    __syncthreads();
    int add = 0;
    for (int w = 0; w < wid; w++) add += ws[w];
    int incl = x + add + g_block_sums[blockIdx.x];
    if (i < N_NODES) {
        g_row_ptr[i + 1] = incl;
        g_cursor[i] = incl - v;
        g_norm_src[i] = rsqrtf(fmaxf((float)g_deg_out_i[i], 1.0f));
        g_norm_dst[i] = rsqrtf(fmaxf((float)g_deg_in_i[i], 1.0f));
        if (i == 0) g_row_ptr[0] = 0;
    }
}

// ---------------- fill CSR (by dst) --------------------------------------------
__global__ void fill_kernel(const int* __restrict__ src,
                            const int* __restrict__ dst) {
    int e = blockIdx.x * blockDim.x + threadIdx.x;
    if (e >= N_EDGES) return;
    int pos = atomicAdd(&g_cursor[dst[e]], 1);
    g_csr_src[pos] = src[e];
}

// ---------------- fused gather + 3-GEMM MLP kernel ------------------------------
// One CTA owns 128 rows:
//   gather: A = norm_dst .* (sum_{src} x_h[src]*norm_src) -> smem A-tile (fp16)
//   h1 = A @ Wc + bc ; relu -> A-tile     (fp16, fp32 accum)
//   h2 = h1 @ Wf + bf ; relu -> A-tile
//   out = h2 @ Wf2 + bf2 -> global fp32
// A/h tile: 8 chunk-slots of [128 rows x 32 k] fp16, row stride 20 words (80B).
// B tile: [256 n x 32 k] fp16, row stride 20 words; 3 rotating cp.async buffers.
// mma.sync.m16n8k16 f16/f32; 512 threads = 16 warps (4m x 4n), warp tile 32x64.

#define RS 20                               // words per 32-fp16 row (+4 pad)
#define CHW   (128 * RS)                    // A chunk words = 2560
#define H_W   (8 * CHW)                     // 20480 words = 81920 B
#define B_W   (256 * RS)                    // 5120 words  = 20480 B
#define FUSED_SMEM ((H_W + 3 * B_W) * 4)    // 143360 B = 140 KB

__device__ __forceinline__ void issue_B(uint32_t buf_saddr, const __half* W,
                                        int k0, int K, int tid) {
    #pragma unroll
    for (int it = 0; it < 2; it++) {
        int f = tid + it * 512;             // 0..1023
        int n = f >> 2, c = f & 3;
        cp16(buf_saddr + (uint32_t)(n * (RS * 4) + c * 16),
             W + (size_t)n * K + k0 + c * 8);
    }
}

__device__ __forceinline__ void mma_chunk(const uint32_t* __restrict__ Aw,
                                          const uint32_t* __restrict__ Bw,
                                          float* acc, int wm, int wn,
                                          int gid, int tig) {
    #pragma unroll
    for (int kq = 0; kq < 2; kq++) {
        uint32_t af[2][4];
        #pragma unroll
        for (int mt = 0; mt < 2; mt++) {
            int r = wm * 32 + mt * 16 + gid;
            int base = r * RS + kq * 8 + tig;
            af[mt][0] = Aw[base];
            af[mt][1] = Aw[base + 8 * RS];
            af[mt][2] = Aw[base + 4];
            af[mt][3] = Aw[base + 8 * RS + 4];
        }
        uint32_t bfr[8][2];
        #pragma unroll
        for (int nt = 0; nt < 8; nt++) {
            int n = wn * 64 + nt * 8 + gid;
            int bb = n * RS + kq * 8 + tig;
            bfr[nt][0] = Bw[bb];
            bfr[nt][1] = Bw[bb + 4];
        }
        #pragma unroll
        for (int mt = 0; mt < 2; mt++) {
            #pragma unroll
            for (int nt = 0; nt < 8; nt++) {
                float* c = &acc[(mt * 8 + nt) * 4];
                asm volatile(
                    "mma.sync.aligned.m16n8k16.row.col.f32.f16.f16.f32 "
                    "{%0,%1,%2,%3},{%4,%5,%6,%7},{%8,%9},{%0,%1,%2,%3};\n"
                    : "+f"(c[0]), "+f"(c[1]), "+f"(c[2]), "+f"(c[3])
                    : "r"(af[mt][0]), "r"(af[mt][1]),
                      "r"(af[mt][2]), "r"(af[mt][3]),
                      "r"(bfr[nt][0]), "r"(bfr[nt][1]));
            }
        }
    }
}

__global__ void __launch_bounds__(512, 1) fused_mlp(
    const __half* __restrict__ Wc,  const float* __restrict__ bc,
    const __half* __restrict__ Wf,  const float* __restrict__ bf,
    const __half* __restrict__ Wf2, const float* __restrict__ bf2,
    float* __restrict__ out, int M)
{
    extern __shared__ uint32_t shw[];
    const uint32_t sb = smem_to_u32(shw);
    const int tid  = threadIdx.x;
    const int lane = tid & 31;
    const int wrp  = tid >> 5;
    const int wm   = wrp & 3;
    const int wn   = wrp >> 2;
    const int gid  = lane >> 2;
    const int tig  = lane & 3;
    const int block_m = blockIdx.x * 128;

    float acc[64];
    #pragma unroll
    for (int i = 0; i < 64; i++) acc[i] = 0.0f;

    // -------- prologue: prefetch B0 of stage 1, then gather into A tile -------
    issue_B(sb + H_W * 4, Wc, 0, IN_F, tid);
    CP_COMMIT();

    // gather: warp wrp handles rows wrp, wrp+16, ..., wrp+112
    // lane covers features lane*4 .. lane*4+3, read as 4 fp16 (8 bytes)
    #pragma unroll 1
    for (int rr = 0; rr < 8; rr++) {
        int r = rr * 16 + wrp;
        int grow = block_m + r;
        float4 a4 = make_float4(0.f, 0.f, 0.f, 0.f);
        if (grow < M) {
            int beg = g_row_ptr[grow];
            int end = g_row_ptr[grow + 1];
            for (int j = beg; j < end; j++) {
                int s = g_csr_src[j];
                float ns = g_norm_src[s];
                uint2 u = reinterpret_cast<const uint2*>(
                              g_x_h + (size_t)s * IN_F)[lane];
                float2 v0 = __half22float2(*reinterpret_cast<__half2*>(&u.x));
                float2 v1 = __half22float2(*reinterpret_cast<__half2*>(&u.y));
                a4.x = fmaf(v0.x, ns, a4.x);
                a4.y = fmaf(v0.y, ns, a4.y);
                a4.z = fmaf(v1.x, ns, a4.z);
                a4.w = fmaf(v1.y, ns, a4.w);
            }
            float nd = g_norm_dst[grow];
            a4.x *= nd; a4.y *= nd; a4.z *= nd; a4.w *= nd;
        }
        uint32_t w = (uint32_t)((lane >> 3) * CHW + r * RS + (lane & 7) * 2);
        __half2 h01 = __floats2half2_rn(a4.x, a4.y);
        __half2 h23 = __floats2half2_rn(a4.z, a4.w);
        *reinterpret_cast<__half2*>(&shw[w])     = h01;
        *reinterpret_cast<__half2*>(&shw[w + 1]) = h23;
    }

    // -------- generic stage runner: 3 B-buffers, one sync per chunk -----------
    auto run_stage = [&](int NCH, const __half* W, int K) {
        for (int ch = 0; ch < NCH; ch++) {
            if (ch + 1 < NCH) {
                issue_B(sb + (H_W + ((ch + 1) % 3) * B_W) * 4, W,
                        (ch + 1) * 32, K, tid);
                CP_COMMIT();
                CP_WAIT1();
            } else {
                CP_WAIT0();
            }
            __syncthreads();
            mma_chunk(shw + ch * CHW, shw + H_W + (ch % 3) * B_W,
                      acc, wm, wn, gid, tig);
        }
    };

    // epilogue: acc -> A tile (bias, relu, fp16), reset acc
    auto epilogue_h = [&](const float* bias) {
        #pragma unroll
        for (int mt = 0; mt < 2; mt++) {
            int r = wm * 32 + mt * 16 + gid;
            #pragma unroll
            for (int nt = 0; nt < 8; nt++) {
                int n = wn * 64 + nt * 8 + tig * 2;
                float b0 = bias[n], b1 = bias[n + 1];
                const float* c = &acc[(mt * 8 + nt) * 4];
                int wbase = (n >> 5) * CHW + ((n & 31) >> 1);
                __half2 lo = __floats2half2_rn(fmaxf(c[0] + b0, 0.f),
                                               fmaxf(c[1] + b1, 0.f));
                __half2 hi = __floats2half2_rn(fmaxf(c[2] + b0, 0.f),
                                               fmaxf(c[3] + b1, 0.f));
                *reinterpret_cast<__half2*>(&shw[wbase + r * RS])       = lo;
                *reinterpret_cast<__half2*>(&shw[wbase + (r + 8) * RS]) = hi;
            }
        }
        #pragma unroll
        for (int i = 0; i < 64; i++) acc[i] = 0.0f;
    };

    // -------- stage 1: h1 = A @ Wc (K=128) ------------------------------------
    run_stage(4, Wc, IN_F);
    __syncthreads();               // all mma done before A overwrite
    epilogue_h(bc);
    issue_B(sb + H_W * 4, Wf, 0, H_F, tid);
    CP_COMMIT();

    // -------- stage 2: h2 = h1 @ Wf (K=256) -----------------------------------
    run_stage(8, Wf, H_F);
    __syncthreads();
    epilogue_h(bf);
    issue_B(sb + H_W * 4, Wf2, 0, H_F, tid);
    CP_COMMIT();

    // -------- stage 3: out = h2 @ Wf2 (K=256) ---------------------------------
    run_stage(8, Wf2, H_F);

    // final epilogue: bias add, fp32 store
    #pragma unroll
    for (int mt = 0; mt < 2; mt++) {
        int r0 = block_m + wm * 32 + mt * 16 + gid;
        #pragma unroll
        for (int nt = 0; nt < 8; nt++) {
            int n = wn * 64 + nt * 8 + tig * 2;
            float b0 = bf2[n], b1 = bf2[n + 1];
            const float* c = &acc[(mt * 8 + nt) * 4];
            if (r0 < M) {
                out[(size_t)r0 * 256 + n]     = c[0] + b0;
                out[(size_t)r0 * 256 + n + 1] = c[1] + b1;
            }
            if (r0 + 8 < M) {
                out[(size_t)(r0 + 8) * 256 + n]     = c[2] + b0;
                out[(size_t)(r0 + 8) * 256 + n + 1] = c[3] + b1;
            }
        }
    }
}

// ---------------- launch ------------------------------------------------------
extern "C" void kernel_launch(void* const* d_in, const int* in_sizes, int n_in,
                              void* d_out, int out_size)
{
    const float* x      = (const float*)d_in[0];
    const int*   src    = (const int*)  d_in[1];
    const int*   dst    = (const int*)  d_in[2];
    const float* W_conv = (const float*)d_in[3];
    const float* b_conv = (const float*)d_in[4];
    const float* W_fc   = (const float*)d_in[5];
    const float* b_fc   = (const float*)d_in[6];
    const float* W_fc2  = (const float*)d_in[7];
    const float* b_fc2  = (const float*)d_in[8];
    float* out = (float*)d_out;

    (void)in_sizes; (void)n_in; (void)out_size;

    __half* wc_ptr;  cudaGetSymbolAddress((void**)&wc_ptr,  g_Wc_h);
    __half* wf_ptr;  cudaGetSymbolAddress((void**)&wf_ptr,  g_Wf_h);
    __half* wf2_ptr; cudaGetSymbolAddress((void**)&wf2_ptr, g_Wf2_h);

    static bool attr_done = false;
    if (!attr_done) {
        cudaFuncSetAttribute(fused_mlp,
                             cudaFuncAttributeMaxDynamicSharedMemorySize,
                             FUSED_SMEM);
        attr_done = true;
    }

    const int EB = (N_EDGES + 255) / 256;

    // init: zero degrees + weight fp16 transpose + x fp16 convert
    init_kernel<<<2048, 256>>>(x, W_conv, W_fc, W_fc2);
    degree_kernel<<<EB, 256>>>(src, dst);

    scan_phaseA<<<NSB, 256>>>();
    scan_phaseB<<<1, 256>>>();
    scan_phaseC<<<NSB, 256>>>();

    fill_kernel<<<EB, 256>>>(src, dst);

    const int GB = (N_NODES + 127) / 128;   // 391 CTAs
    fused_mlp<<<GB, 512, FUSED_SMEM>>>(wc_ptr, b_conv,
                                       wf_ptr, b_fc,
                                       wf2_ptr, b_fc2,
                                       out, N_NODES);
}